// round 16
// baseline (speedup 1.0000x reference)
#include <cuda_runtime.h>

// Fused pre-norm attention-downsampling:
//   out[b,s,:] = q[b,s,:] + sum_f (LN(q[b,s]) . LN(k[b,4s+f])) * LN(v[b,4s+f])
// B=4, Sq=2048, Skv=8192, D=1024, factor=4.
// R15: R12's validated row math, persistent grid-stride CTAs (740 = 148 SMs
// x 5 CTAs) + prefetch.global.L2 of the NEXT row (bid + gridDim.x) issued
// during the current row's compute. Cross-row DRAM/compute overlap with zero
// register or smem cost; next iteration's LDGs hit L2.

#define DD 1024
#define NT 256
#define NW 8
#define FACTOR 4
#define LN_EPS 1e-5f
#define NROWS 8192
#define WSTRIDE 96            // 12 values * 8 partials per warp (floats)
#define SMB (NW * WSTRIDE)    // 768 floats of partials; bcast region after

// Batched block reduction of N values (N <= 12), 2-level butterfly, 2 barriers.
template <int N>
__device__ __forceinline__ void block_reduce(float (&val)[N], float* sm) {
#pragma unroll
    for (int i = 0; i < N; i++) {
        val[i] += __shfl_xor_sync(0xffffffffu, val[i], 16);
        val[i] += __shfl_xor_sync(0xffffffffu, val[i], 8);
    }
    const int w = threadIdx.x >> 5;
    const int l = threadIdx.x & 31;
    if (l < 8) {
#pragma unroll
        for (int i = 0; i < N; i++) sm[w * WSTRIDE + i * 8 + l] = val[i];
    }
    __syncthreads();
    if (threadIdx.x < N) {
        float tot = 0.f;
#pragma unroll
        for (int j = 0; j < NW; j++) {
            const float4 p0 =
                *(const float4*)&sm[j * WSTRIDE + threadIdx.x * 8];
            const float4 p1 =
                *(const float4*)&sm[j * WSTRIDE + threadIdx.x * 8 + 4];
            tot += ((p0.x + p0.y) + (p0.z + p0.w)) +
                   ((p1.x + p1.y) + (p1.z + p1.w));
        }
        sm[SMB + threadIdx.x] = tot;
    }
    __syncthreads();
#pragma unroll
    for (int i = 0; i < N; i += 4) {
        const float4 bb = *(const float4*)&sm[SMB + i];
        val[i] = bb.x;
        if (i + 1 < N) val[i + 1] = bb.y;
        if (i + 2 < N) val[i + 2] = bb.z;
        if (i + 3 < N) val[i + 3] = bb.w;
    }
}

__device__ __forceinline__ float hsum(const float4 a) {
    return (a.x + a.y) + (a.z + a.w);
}
__device__ __forceinline__ float hsq(const float4 a) {
    return (a.x * a.x + a.y * a.y) + (a.z * a.z + a.w * a.w);
}
__device__ __forceinline__ void pf_l2(const float* p) {
    asm volatile("prefetch.global.L2 [%0];" ::"l"(p));
}

__global__ __launch_bounds__(NT, 5) void attn_ds_kernel(
    const float* __restrict__ q, const float* __restrict__ k,
    const float* __restrict__ v, const float* __restrict__ lnw,
    const float* __restrict__ lnb, float* __restrict__ out) {
    __shared__ __align__(16) float sm[SMB + 12];

    const int t = threadIdx.x;
    const float invD = 1.0f / (float)DD;

    // Loop-invariant: LN params in registers.
    const float4 wv = ((const float4*)lnw)[t];
    const float4 bv = ((const float4*)lnb)[t];

    for (int bid = blockIdx.x; bid < NROWS; bid += gridDim.x) {
        const int b = bid >> 11;
        const int s = bid & 2047;

        const float4* q4 = (const float4*)q + (size_t)bid * (DD / 4);
        const size_t kvo = ((size_t)b * 8192 + (size_t)s * FACTOR) * (DD / 4);
        const float4* k4 = (const float4*)k + kvo;
        const float4* v4 = (const float4*)v + kvo;

        // Front-batched loads for phase 1: q + 4k (5 LDG.128).
        const float4 qv = q4[t];
        float4 kr[FACTOR];
#pragma unroll
        for (int f = 0; f < FACTOR; f++) kr[f] = k4[f * (DD / 4) + t];

        // ---- L2 prefetch of the NEXT row this CTA will process ----
        {
            const int nb = bid + gridDim.x;
            if (nb < NROWS) {
                const float* qn = q + (size_t)nb * DD;
                const size_t nkv =
                    ((size_t)(nb >> 11) * 8192 +
                     (size_t)(nb & 2047) * FACTOR) * DD;
                if (t < 32) pf_l2(qn + t * 32);          // 4 KB of q
                if (t < 128) pf_l2(k + nkv + t * 32);    // 16 KB of k
                else pf_l2(v + nkv + (t - 128) * 32);    // 16 KB of v
            }
        }

        // ---- Phase 1: q + k stats (10 values, one reduction) ----
        float r1[10];
        r1[0] = hsum(qv);
        r1[1] = hsq(qv);
#pragma unroll
        for (int f = 0; f < FACTOR; f++) {
            r1[2 + 2 * f] = hsum(kr[f]);
            r1[3 + 2 * f] = hsq(kr[f]);
        }
        block_reduce<10>(r1, sm);

        const float mu = r1[0] * invD;
        const float rs = rsqrtf(fmaf(-mu, mu, r1[1] * invD) + LN_EPS);
        float4 qn;
        qn.x = fmaf((qv.x - mu) * rs, wv.x, bv.x);
        qn.y = fmaf((qv.y - mu) * rs, wv.y, bv.y);
        qn.z = fmaf((qv.z - mu) * rs, wv.z, bv.z);
        qn.w = fmaf((qv.w - mu) * rs, wv.w, bv.w);

        // ---- Phase 2: dot partials; v_f loaded as k_f dies ----
        float4 vr[FACTOR];
        float r2[12];
#pragma unroll
        for (int f = 0; f < FACTOR; f++) {
            const float muk = r1[2 + 2 * f] * invD;
            const float rsk =
                rsqrtf(fmaf(-muk, muk, r1[3 + 2 * f] * invD) + LN_EPS);
            const float4 kv = kr[f];
            const float knx = fmaf((kv.x - muk) * rsk, wv.x, bv.x);
            const float kny = fmaf((kv.y - muk) * rsk, wv.y, bv.y);
            const float knz = fmaf((kv.z - muk) * rsk, wv.z, bv.z);
            const float knw = fmaf((kv.w - muk) * rsk, wv.w, bv.w);
            r2[f] = (knx * qn.x + kny * qn.y) + (knz * qn.z + knw * qn.w);
            vr[f] = v4[f * (DD / 4) + t];   // k_f register slots freed -> v_f
        }
#pragma unroll
        for (int f = 0; f < FACTOR; f++) {
            r2[4 + f] = hsum(vr[f]);
            r2[8 + f] = hsq(vr[f]);
        }
        block_reduce<12>(r2, sm);

        // ---- Epilogue: residual + weighted LN(v) ----
        float4 acc = qv;
#pragma unroll
        for (int f = 0; f < FACTOR; f++) {
            const float wt = r2[f];
            const float muv = r2[4 + f] * invD;
            const float rsv =
                rsqrtf(fmaf(-muv, muv, r2[8 + f] * invD) + LN_EPS);
            const float4 vv = vr[f];
            acc.x = fmaf(wt, fmaf((vv.x - muv) * rsv, wv.x, bv.x), acc.x);
            acc.y = fmaf(wt, fmaf((vv.y - muv) * rsv, wv.y, bv.y), acc.y);
            acc.z = fmaf(wt, fmaf((vv.z - muv) * rsv, wv.z, bv.z), acc.z);
            acc.w = fmaf(wt, fmaf((vv.w - muv) * rsv, wv.w, bv.w), acc.w);
        }

        ((float4*)out + (size_t)bid * (DD / 4))[t] = acc;
    }
}

extern "C" void kernel_launch(void* const* d_in, const int* in_sizes, int n_in,
                              void* d_out, int out_size) {
    const float* q   = (const float*)d_in[0];  // query     [4,2048,1024]
    const float* k   = (const float*)d_in[1];  // key       [4,8192,1024]
    const float* v   = (const float*)d_in[2];  // value     [4,8192,1024]
    const float* lnw = (const float*)d_in[3];  // ln_weight [1024]
    const float* lnb = (const float*)d_in[4];  // ln_bias   [1024]
    float* out = (float*)d_out;                // [4,2048,1024]

    attn_ds_kernel<<<148 * 5, NT>>>(q, k, v, lnw, lnb, out);
}

// round 17
// speedup vs baseline: 1.2392x; 1.2392x over previous
#include <cuda_runtime.h>
#include <cstdint>

// Fused pre-norm attention-downsampling:
//   out[b,s,:] = q[b,s,:] + sum_f (LN(q[b,s]) . LN(k[b,4s+f])) * LN(v[b,4s+f])
// B=4, Sq=2048, Skv=8192, D=1024, factor=4.
// R16: R12 (one CTA per row, cheap 2-level reduction, deferred v) with the v
// stream moved off the LDG path: ONE cp.async.bulk (16 KB) issued at CTA
// start copies all 4 v rows into smem while q/k loads + phase 1 + dots run.
// Phase 2 reads v from smem at LDS latency -> the ~500-cycle pre-reduce2
// stall disappears, and L1tex loses 40% of its LDG wavefronts.

#define DD 1024
#define NT 256
#define NW 8
#define FACTOR 4
#define LN_EPS 1e-5f
#define WSTRIDE 96            // 12 values * 8 partials per warp (floats)
#define SMB (NW * WSTRIDE)    // 768 floats of partials; bcast region after
#define V_BYTES (FACTOR * DD * 4)   // 16384

// Batched block reduction of N values (N <= 12), 2-level butterfly, 2 barriers.
template <int N>
__device__ __forceinline__ void block_reduce(float (&val)[N], float* sm) {
#pragma unroll
    for (int i = 0; i < N; i++) {
        val[i] += __shfl_xor_sync(0xffffffffu, val[i], 16);
        val[i] += __shfl_xor_sync(0xffffffffu, val[i], 8);
    }
    const int w = threadIdx.x >> 5;
    const int l = threadIdx.x & 31;
    if (l < 8) {
#pragma unroll
        for (int i = 0; i < N; i++) sm[w * WSTRIDE + i * 8 + l] = val[i];
    }
    __syncthreads();
    if (threadIdx.x < N) {
        float tot = 0.f;
#pragma unroll
        for (int j = 0; j < NW; j++) {
            const float4 p0 =
                *(const float4*)&sm[j * WSTRIDE + threadIdx.x * 8];
            const float4 p1 =
                *(const float4*)&sm[j * WSTRIDE + threadIdx.x * 8 + 4];
            tot += ((p0.x + p0.y) + (p0.z + p0.w)) +
                   ((p1.x + p1.y) + (p1.z + p1.w));
        }
        sm[SMB + threadIdx.x] = tot;
    }
    __syncthreads();
#pragma unroll
    for (int i = 0; i < N; i += 4) {
        const float4 bb = *(const float4*)&sm[SMB + i];
        val[i] = bb.x;
        if (i + 1 < N) val[i + 1] = bb.y;
        if (i + 2 < N) val[i + 2] = bb.z;
        if (i + 3 < N) val[i + 3] = bb.w;
    }
}

__device__ __forceinline__ float hsum(const float4 a) {
    return (a.x + a.y) + (a.z + a.w);
}
__device__ __forceinline__ float hsq(const float4 a) {
    return (a.x * a.x + a.y * a.y) + (a.z * a.z + a.w * a.w);
}

// ---- mbarrier / bulk-async helpers ----
__device__ __forceinline__ void mbar_init(uint32_t mbar, uint32_t cnt) {
    asm volatile("mbarrier.init.shared.b64 [%0], %1;" ::"r"(mbar), "r"(cnt)
                 : "memory");
}
__device__ __forceinline__ void mbar_expect_tx(uint32_t mbar, uint32_t bytes) {
    asm volatile("mbarrier.arrive.expect_tx.shared.b64 _, [%0], %1;" ::"r"(mbar),
                 "r"(bytes)
                 : "memory");
}
__device__ __forceinline__ void bulk_g2s(uint32_t dst, const void* src,
                                         uint32_t bytes, uint32_t mbar) {
    asm volatile(
        "cp.async.bulk.shared::cta.global.mbarrier::complete_tx::bytes "
        "[%0], [%1], %2, [%3];" ::"r"(dst),
        "l"(src), "r"(bytes), "r"(mbar)
        : "memory");
}
__device__ __forceinline__ void mbar_wait(uint32_t mbar, uint32_t parity) {
    uint32_t done;
    asm volatile(
        "{\n\t.reg .pred p;\n\t"
        "mbarrier.try_wait.parity.acquire.cta.shared::cta.b64 p, [%1], %2;\n\t"
        "selp.b32 %0, 1, 0, p;\n\t}"
        : "=r"(done)
        : "r"(mbar), "r"(parity)
        : "memory");
    if (!done) {
        asm volatile(
            "{\n\t.reg .pred P1;\n\t"
            "WL_%=:\n\t"
            "mbarrier.try_wait.parity.acquire.cta.shared::cta.b64 P1, [%0], %1;\n\t"
            "@P1 bra.uni WD_%=;\n\t"
            "bra.uni WL_%=;\n\t"
            "WD_%=:\n\t}" ::"r"(mbar),
            "r"(parity)
            : "memory");
    }
}

__global__ __launch_bounds__(NT, 5) void attn_ds_kernel(
    const float* __restrict__ q, const float* __restrict__ k,
    const float* __restrict__ v, const float* __restrict__ lnw,
    const float* __restrict__ lnb, float* __restrict__ out) {
    __shared__ __align__(16) float sm[SMB + 12];
    __shared__ __align__(16) float4 sv[FACTOR * (DD / 4)];  // 16 KB v tile
    __shared__ __align__(8) unsigned long long mbar_s;

    const int bid = blockIdx.x;          // b*2048 + s
    const int b = bid >> 11;
    const int s = bid & 2047;
    const int t = threadIdx.x;
    const float invD = 1.0f / (float)DD;

    const float4* q4 = (const float4*)q + (size_t)bid * (DD / 4);
    const size_t kvo = ((size_t)b * 8192 + (size_t)s * FACTOR) * (DD / 4);
    const float4* k4 = (const float4*)k + kvo;

    // ---- t0: kick off the v bulk copy immediately (overlaps everything) ----
    const uint32_t mbar = (uint32_t)__cvta_generic_to_shared(&mbar_s);
    if (t == 0) {
        mbar_init(mbar, 1);
        mbar_expect_tx(mbar, V_BYTES);
        bulk_g2s((uint32_t)__cvta_generic_to_shared(sv),
                 (const float4*)v + kvo, V_BYTES, mbar);
    }

    // Front-batched LDGs for phase 1: q + 4k + w/b (7 LDG.128).
    const float4 qv = q4[t];
    const float4 wv = ((const float4*)lnw)[t];
    const float4 bv = ((const float4*)lnb)[t];
    float4 kr[FACTOR];
#pragma unroll
    for (int f = 0; f < FACTOR; f++) kr[f] = k4[f * (DD / 4) + t];

    // ---- Phase 1: q + k stats (10 values, one reduction) ----
    // (reduce1's __syncthreads also makes the mbarrier init visible to all.)
    float r1[10];
    r1[0] = hsum(qv);
    r1[1] = hsq(qv);
#pragma unroll
    for (int f = 0; f < FACTOR; f++) {
        r1[2 + 2 * f] = hsum(kr[f]);
        r1[3 + 2 * f] = hsq(kr[f]);
    }
    block_reduce<10>(r1, sm);

    const float mu = r1[0] * invD;
    const float rs = rsqrtf(fmaf(-mu, mu, r1[1] * invD) + LN_EPS);
    float4 qn;
    qn.x = fmaf((qv.x - mu) * rs, wv.x, bv.x);
    qn.y = fmaf((qv.y - mu) * rs, wv.y, bv.y);
    qn.z = fmaf((qv.z - mu) * rs, wv.z, bv.z);
    qn.w = fmaf((qv.w - mu) * rs, wv.w, bv.w);

    // ---- Phase 2: dot partials (kr dies) ----
    float r2[12];
#pragma unroll
    for (int f = 0; f < FACTOR; f++) {
        const float muk = r1[2 + 2 * f] * invD;
        const float rsk =
            rsqrtf(fmaf(-muk, muk, r1[3 + 2 * f] * invD) + LN_EPS);
        const float4 kv = kr[f];
        const float knx = fmaf((kv.x - muk) * rsk, wv.x, bv.x);
        const float kny = fmaf((kv.y - muk) * rsk, wv.y, bv.y);
        const float knz = fmaf((kv.z - muk) * rsk, wv.z, bv.z);
        const float knw = fmaf((kv.w - muk) * rsk, wv.w, bv.w);
        r2[f] = (knx * qn.x + kny * qn.y) + (knz * qn.z + knw * qn.w);
    }

    // ---- v from smem (copy long since complete; LDS latency only) ----
    mbar_wait(mbar, 0);
    float4 vr[FACTOR];
#pragma unroll
    for (int f = 0; f < FACTOR; f++) vr[f] = sv[f * (DD / 4) + t];
#pragma unroll
    for (int f = 0; f < FACTOR; f++) {
        r2[4 + f] = hsum(vr[f]);
        r2[8 + f] = hsq(vr[f]);
    }
    block_reduce<12>(r2, sm);

    // ---- Epilogue: residual + weighted LN(v) ----
    float4 acc = qv;
#pragma unroll
    for (int f = 0; f < FACTOR; f++) {
        const float wt = r2[f];
        const float muv = r2[4 + f] * invD;
        const float rsv =
            rsqrtf(fmaf(-muv, muv, r2[8 + f] * invD) + LN_EPS);
        const float4 vv = vr[f];
        acc.x = fmaf(wt, fmaf((vv.x - muv) * rsv, wv.x, bv.x), acc.x);
        acc.y = fmaf(wt, fmaf((vv.y - muv) * rsv, wv.y, bv.y), acc.y);
        acc.z = fmaf(wt, fmaf((vv.z - muv) * rsv, wv.z, bv.z), acc.z);
        acc.w = fmaf(wt, fmaf((vv.w - muv) * rsv, wv.w, bv.w), acc.w);
    }

    ((float4*)out + (size_t)bid * (DD / 4))[t] = acc;
}

extern "C" void kernel_launch(void* const* d_in, const int* in_sizes, int n_in,
                              void* d_out, int out_size) {
    const float* q   = (const float*)d_in[0];  // query     [4,2048,1024]
    const float* k   = (const float*)d_in[1];  // key       [4,8192,1024]
    const float* v   = (const float*)d_in[2];  // value     [4,8192,1024]
    const float* lnw = (const float*)d_in[3];  // ln_weight [1024]
    const float* lnb = (const float*)d_in[4];  // ln_bias   [1024]
    float* out = (float*)d_out;                // [4,2048,1024]

    attn_ds_kernel<<<4 * 2048, NT>>>(q, k, v, lnw, lnb, out);
}